// round 10
// baseline (speedup 1.0000x reference)
#include <cuda_runtime.h>
#include <cuda_fp16.h>

#define BB 2
#define LL 16
#define CC 16
#define HH 64
#define WW 64
#define HW (HH*WW)

#define PW 68                 // padded width in 32B pixel-chunks; 68*32 = 2176 = 17*128
#define PH 66                 // padded height (rows -1..64)
#define PCH (PW*PH)
#define IMG_BYTES (PCH*32)    // 143616

// Zero-padded channel-last fp16 image cache. Chunk (y,x) (32B = 16 halves) at
// chunk index (y+1)*PW + (x+1), for x,y in [-1,64].
__device__ uint4 g_pad[BB*LL*PCH*2];

// ---------------------------------------------------------------------------
// Kernel 1: images (B,L,C,H,W) fp32 -> padded channel-last fp16 (zero border)
// ---------------------------------------------------------------------------
__global__ __launch_bounds__(256) void pad_kernel(const float* __restrict__ images) {
    int i = blockIdx.x * 256 + threadIdx.x;      // [0, BB*LL*PCH)
    int bl = i / PCH;
    int s  = i - bl * PCH;
    int y  = s / PW;
    int x  = s - y * PW;
    uint4 v0 = make_uint4(0u,0u,0u,0u), v1 = v0;
    if (x >= 1 && x <= WW && y >= 1 && y <= HH) {
        int px = (y - 1) * WW + (x - 1);
        const float* sp = images + (size_t)bl * CC * HW + px;
        unsigned u[8];
#pragma unroll
        for (int c = 0; c < 8; c++) {
            __half2 hh = __floats2half2_rn(sp[(2*c) * HW], sp[(2*c+1) * HW]);
            u[c] = *(unsigned*)&hh;
        }
        v0 = make_uint4(u[0], u[1], u[2], u[3]);
        v1 = make_uint4(u[4], u[5], u[6], u[7]);
    }
    uint4* d = g_pad + (size_t)i * 2;
    d[0] = v0;
    d[1] = v1;
}

// ---------------------------------------------------------------------------
// Per-k body pieces shared by the main loop.
// ---------------------------------------------------------------------------
struct KW { const char* addr; __half2 wt2, wb2; };

__device__ __forceinline__ KW kweights(float2 ck, float cwx, float cwy,
                                       int xq, const char* kb) {
    float uxp = fmaf(-32.0f, ck.x, cwx);
    float uyp = fmaf(-32.0f, ck.y, cwy);
    // mod into [0,64): rxm == true rx + 0.5
    float rxm = fmaf(-floorf(uxp * 0.015625f), 64.0f, uxp);
    float rym = fmaf(-floorf(uyp * 0.015625f), 64.0f, uyp);
    float rx0 = rxm - 0.5f;
    float ry0 = rym - 0.5f;
    float fx0 = floorf(rx0);
    float fy0 = floorf(ry0);
    int x0 = (int)fx0;        // [-1, 63]
    int y0 = (int)fy0;
    float sx = rx0 - fx0;
    float sy = ry0 - fy0;
    float xw = xq ? sx : (1.0f - sx);
    KW kw;
    kw.wt2  = __float2half2_rn(xw * (1.0f - sy));
    kw.wb2  = __float2half2_rn(xw * sy);
    kw.addr = kb + (y0 * PW + x0) * 32;
    return kw;
}

// ---------------------------------------------------------------------------
// Kernel 2: main. 4 lanes per pixel (q = (xq<<1)|cq) — wavefront-optimal.
// k-loop unrolled x2 with independent fp16 accumulator sets (even/odd k):
// doubles memory-level parallelism and halves fp16 accumulation chains.
// Blocks compute paired timesteps (15-r, r): uniform 17 k-iters per block.
// ---------------------------------------------------------------------------
__global__ __launch_bounds__(256) void main_kernel(const float* __restrict__ flows,
                                                   float* __restrict__ out) {
    __shared__ float2 scum[LL * 64];

    int idx = blockIdx.x;             // [0, 1024): b(2) x r(8) x blk(64)
    int blk = idx & 63;
    int r   = (idx >> 6) & 7;
    int b   = idx >> 9;
    int p_base = blk * 64;
    int tid = threadIdx.x;

    // Fused cumsum: threads 0..127 = 64 pixels x 2 components.
    if (tid < 128) {
        int comp = tid >> 6;
        int pl   = tid & 63;
        const float* fb = flows + ((size_t)b * LL * 2 + comp) * HW + p_base + pl;
        float c = 0.0f;
#pragma unroll
        for (int l = 0; l < LL; l++) {
            c += fb[l * 2 * HW];
            ((float*)&scum[l * 64 + pl])[comp] = c;
        }
    }
    __syncthreads();

    int pl = tid >> 2;
    int q  = tid & 3;
    int xq = q >> 1;                  // left/right column
    int cq = q & 1;                   // channel octet
    int p  = p_base + pl;
    int h  = p >> 6;
    int w  = p & 63;
    float wc = (w + 0.5f);
    float hc = (h + 0.5f);

    // base ptr: image series + (+1,+1) pad origin + lane column/octet offset
    const char* ib0 = (const char*)g_pad
                    + (size_t)(b * LL) * IMG_BYTES
                    + (size_t)((PW + 1 + xq) * 32 + cq * 16);

#pragma unroll
    for (int pass = 0; pass < 2; pass++) {
        int t = pass ? r : (15 - r);

        float2 ct = scum[t * 64 + pl];
        float cwx = fmaf(32.0f, ct.x, wc);
        float cwy = fmaf(32.0f, ct.y, hc);

        __half2 zero = __float2half2_rn(0.0f);
        __half2 a0 = zero, a1 = zero, a2 = zero, a3 = zero;   // even k
        __half2 b0 = zero, b1 = zero, b2 = zero, b3 = zero;   // odd k

        int k = 0;
        const char* kb = ib0;
#pragma unroll 1
        for (; k + 1 <= t; k += 2, kb += 2 * IMG_BYTES) {
            float2 ckA = scum[k * 64 + pl];
            float2 ckB = scum[(k + 1) * 64 + pl];
            KW kwA = kweights(ckA, cwx, cwy, xq, kb);
            KW kwB = kweights(ckB, cwx, cwy, xq, kb + IMG_BYTES);

            uint4 topA = *(const uint4*)(kwA.addr);
            uint4 botA = *(const uint4*)(kwA.addr + PW * 32);
            uint4 topB = *(const uint4*)(kwB.addr);
            uint4 botB = *(const uint4*)(kwB.addr + PW * 32);

            const __half2* tA = (const __half2*)&topA;
            const __half2* bA = (const __half2*)&botA;
            a0 = __hfma2(tA[0], kwA.wt2, a0);  a0 = __hfma2(bA[0], kwA.wb2, a0);
            a1 = __hfma2(tA[1], kwA.wt2, a1);  a1 = __hfma2(bA[1], kwA.wb2, a1);
            a2 = __hfma2(tA[2], kwA.wt2, a2);  a2 = __hfma2(bA[2], kwA.wb2, a2);
            a3 = __hfma2(tA[3], kwA.wt2, a3);  a3 = __hfma2(bA[3], kwA.wb2, a3);

            const __half2* tB = (const __half2*)&topB;
            const __half2* bB = (const __half2*)&botB;
            b0 = __hfma2(tB[0], kwB.wt2, b0);  b0 = __hfma2(bB[0], kwB.wb2, b0);
            b1 = __hfma2(tB[1], kwB.wt2, b1);  b1 = __hfma2(bB[1], kwB.wb2, b1);
            b2 = __hfma2(tB[2], kwB.wt2, b2);  b2 = __hfma2(bB[2], kwB.wb2, b2);
            b3 = __hfma2(tB[3], kwB.wt2, b3);  b3 = __hfma2(bB[3], kwB.wb2, b3);
        }
        if (k <= t) {                 // tail (t even)
            float2 ckA = scum[k * 64 + pl];
            KW kwA = kweights(ckA, cwx, cwy, xq, kb);
            uint4 topA = *(const uint4*)(kwA.addr);
            uint4 botA = *(const uint4*)(kwA.addr + PW * 32);
            const __half2* tA = (const __half2*)&topA;
            const __half2* bA = (const __half2*)&botA;
            a0 = __hfma2(tA[0], kwA.wt2, a0);  a0 = __hfma2(bA[0], kwA.wb2, a0);
            a1 = __hfma2(tA[1], kwA.wt2, a1);  a1 = __hfma2(bA[1], kwA.wb2, a1);
            a2 = __hfma2(tA[2], kwA.wt2, a2);  a2 = __hfma2(bA[2], kwA.wb2, a2);
            a3 = __hfma2(tA[3], kwA.wt2, a3);  a3 = __hfma2(bA[3], kwA.wb2, a3);
        }

        // Combine even/odd sets, then merge left/right columns (lane q^2).
        __half2 accv[4];
        accv[0] = __hadd2(a0, b0);
        accv[1] = __hadd2(a1, b1);
        accv[2] = __hadd2(a2, b2);
        accv[3] = __hadd2(a3, b3);
#pragma unroll
        for (int j = 0; j < 4; j++) {
            unsigned v = __shfl_xor_sync(0xffffffffu, *(unsigned*)&accv[j], 2);
            accv[j] = __hadd2(accv[j], *(__half2*)&v);
        }

        if (xq == 0) {
            // out layout (B,L,C,H,W); this lane owns channels [cq*8, cq*8+8)
            float* ob = out + ((size_t)(b * LL + t) * CC + cq * 8) * HW + p;
#pragma unroll
            for (int j = 0; j < 4; j++) {
                float2 f = __half22float2(accv[j]);
                ob[(2*j)     * HW] = f.x;
                ob[(2*j + 1) * HW] = f.y;
            }
        }
    }
}

// ---------------------------------------------------------------------------
extern "C" void kernel_launch(void* const* d_in, const int* in_sizes, int n_in,
                              void* d_out, int out_size) {
    const float* flows  = (const float*)d_in[0];
    const float* images = (const float*)d_in[1];
    if (n_in >= 2 && in_sizes[0] > in_sizes[1]) {   // defensive: flows is smaller
        const float* tmp = flows; flows = images; images = tmp;
    }
    float* out = (float*)d_out;

    pad_kernel<<<(BB * LL * PCH + 255) / 256, 256>>>(images);
    main_kernel<<<BB * 8 * 64, 256>>>(flows, out);
}

// round 11
// speedup vs baseline: 1.1009x; 1.1009x over previous
#include <cuda_runtime.h>
#include <cuda_fp16.h>

#define BB 2
#define LL 16
#define CC 16
#define HH 64
#define WW 64
#define HW (HH*WW)

#define PW 68                 // padded width in 32B pixel-chunks; 68*32 = 2176 = 17*128
#define PH 66                 // padded height (rows -1..64)
#define PCH (PW*PH)
#define IMG_BYTES (PCH*32)    // 143616

// Zero-padded channel-last fp16 image cache. Chunk (y,x) (32B = 16 halves) at
// chunk index (y+1)*PW + (x+1), for x,y in [-1,64].
__device__ uint4 g_pad[BB*LL*PCH*2];

// ---------------------------------------------------------------------------
// Kernel 1: images (B,L,C,H,W) fp32 -> padded channel-last fp16 (zero border)
// ---------------------------------------------------------------------------
__global__ __launch_bounds__(256) void pad_kernel(const float* __restrict__ images) {
    int i = blockIdx.x * 256 + threadIdx.x;      // [0, BB*LL*PCH)
    int bl = i / PCH;
    int s  = i - bl * PCH;
    int y  = s / PW;
    int x  = s - y * PW;
    uint4 v0 = make_uint4(0u,0u,0u,0u), v1 = v0;
    if (x >= 1 && x <= WW && y >= 1 && y <= HH) {
        int px = (y - 1) * WW + (x - 1);
        const float* sp = images + (size_t)bl * CC * HW + px;
        unsigned u[8];
#pragma unroll
        for (int c = 0; c < 8; c++) {
            __half2 hh = __floats2half2_rn(sp[(2*c) * HW], sp[(2*c+1) * HW]);
            u[c] = *(unsigned*)&hh;
        }
        v0 = make_uint4(u[0], u[1], u[2], u[3]);
        v1 = make_uint4(u[4], u[5], u[6], u[7]);
    }
    uint4* d = g_pad + (size_t)i * 2;
    d[0] = v0;
    d[1] = v1;
}

// ---------------------------------------------------------------------------
// Kernel 2: main. 4 lanes per pixel (q = (xq<<1)|cq) — wavefront-optimal
// mapping (the 4 lanes of a pixel cover a contiguous 64B span per corner row).
// One (b,t) per block group, heavy-t first; fp16 accumulators, regs <= 32
// so 8 blocks (64 warps) fit per SM.
// ---------------------------------------------------------------------------
__global__ __launch_bounds__(256) void main_kernel(const float* __restrict__ flows,
                                                   float* __restrict__ out) {
    __shared__ float2 scum[LL * 64];

    int bt  = blockIdx.x >> 6;        // 64 blocks per (b,t), 64 pixels each
    int blk = blockIdx.x & 63;
    int b   = bt >> 4;
    int t   = 15 - (bt & 15);         // heavy blocks first
    int p_base = blk * 64;
    int tid = threadIdx.x;

    // Fused cumsum: threads 0..127 = 64 pixels x 2 components.
    if (tid < 128) {
        int comp = tid >> 6;
        int pl   = tid & 63;
        const float* fb = flows + ((size_t)b * LL * 2 + comp) * HW + p_base + pl;
        float c = 0.0f;
#pragma unroll
        for (int l = 0; l < LL; l++) {
            c += fb[l * 2 * HW];
            ((float*)&scum[l * 64 + pl])[comp] = c;
        }
    }
    __syncthreads();

    int pl = tid >> 2;
    int q  = tid & 3;
    int xq = q >> 1;                  // left/right column
    int cq = q & 1;                   // channel octet
    int p  = p_base + pl;
    int h  = p >> 6;
    int w  = p & 63;

    float2 ct = scum[t * 64 + pl];
    float cwx = fmaf(32.0f, ct.x, (w + 0.5f));
    float cwy = fmaf(32.0f, ct.y, (h + 0.5f));

    __half2 zero = __float2half2_rn(0.0f);
    __half2 acc0 = zero, acc1 = zero, acc2 = zero, acc3 = zero;

    // base ptr: image series + (+1,+1) pad origin + lane column/octet offset
    const char* kb = (const char*)g_pad
                   + (size_t)(b * LL) * IMG_BYTES
                   + (size_t)((PW + 1 + xq) * 32 + cq * 16);

#pragma unroll 1
    for (int k = 0; k <= t; k++, kb += IMG_BYTES) {
        float2 ck = scum[k * 64 + pl];
        float uxp = fmaf(-32.0f, ck.x, cwx);
        float uyp = fmaf(-32.0f, ck.y, cwy);
        // mod into [0,64): rxm == true rx + 0.5
        float rxm = fmaf(-floorf(uxp * 0.015625f), 64.0f, uxp);
        float rym = fmaf(-floorf(uyp * 0.015625f), 64.0f, uyp);
        float rx0 = rxm - 0.5f;
        float ry0 = rym - 0.5f;
        float fx0 = floorf(rx0);
        float fy0 = floorf(ry0);
        int x0 = (int)fx0;            // [-1, 63]
        int y0 = (int)fy0;
        float sx = rx0 - fx0;
        float sy = ry0 - fy0;

        float xw = xq ? sx : (1.0f - sx);   // this lane's column weight
        __half2 wt2 = __float2half2_rn(xw * (1.0f - sy));
        __half2 wb2 = __float2half2_rn(xw * sy);

        const char* addr = kb + (y0 * PW + x0) * 32;
        uint4 top = *(const uint4*)(addr);
        uint4 bot = *(const uint4*)(addr + PW * 32);

        const __half2* tp = (const __half2*)&top;
        const __half2* bp = (const __half2*)&bot;
        acc0 = __hfma2(tp[0], wt2, acc0);  acc0 = __hfma2(bp[0], wb2, acc0);
        acc1 = __hfma2(tp[1], wt2, acc1);  acc1 = __hfma2(bp[1], wb2, acc1);
        acc2 = __hfma2(tp[2], wt2, acc2);  acc2 = __hfma2(bp[2], wb2, acc2);
        acc3 = __hfma2(tp[3], wt2, acc3);  acc3 = __hfma2(bp[3], wb2, acc3);
    }

    // Merge left/right columns (partner lane q^2: same pixel, same octet)
    __half2 accv[4] = {acc0, acc1, acc2, acc3};
#pragma unroll
    for (int j = 0; j < 4; j++) {
        unsigned v = __shfl_xor_sync(0xffffffffu, *(unsigned*)&accv[j], 2);
        accv[j] = __hadd2(accv[j], *(__half2*)&v);
    }

    if (xq == 0) {
        // out layout (B,L,C,H,W); this lane owns channels [cq*8, cq*8+8)
        float* ob = out + ((size_t)(b * LL + t) * CC + cq * 8) * HW + p;
#pragma unroll
        for (int j = 0; j < 4; j++) {
            float2 f = __half22float2(accv[j]);
            ob[(2*j)     * HW] = f.x;
            ob[(2*j + 1) * HW] = f.y;
        }
    }
}

// ---------------------------------------------------------------------------
extern "C" void kernel_launch(void* const* d_in, const int* in_sizes, int n_in,
                              void* d_out, int out_size) {
    const float* flows  = (const float*)d_in[0];
    const float* images = (const float*)d_in[1];
    if (n_in >= 2 && in_sizes[0] > in_sizes[1]) {   // defensive: flows is smaller
        const float* tmp = flows; flows = images; images = tmp;
    }
    float* out = (float*)d_out;

    pad_kernel<<<(BB * LL * PCH + 255) / 256, 256>>>(images);
    main_kernel<<<BB * LL * 64, 256>>>(flows, out);
}